// round 8
// baseline (speedup 1.0000x reference)
#include <cuda_runtime.h>
#include <cuda_bf16.h>
#include <cstdint>

// DotAttentionEluX — math collapses:
//   attn[i,j] = ks_j / sum_j ks_j  (query cancels in row normalization)
//   out[b,h,i,:] = (sum_j ks_j * v_j) / (sum_j ks_j)   -- same for every row i
// with ks_j = sum_d (elu(k[b,h,j,d]) + 1).
//
// Evidence R4-R7: 16MB output write pins at ~7us / 2.3TB/s regardless of
// mechanism (STG/TMA/occupancy) with DRAM idle -> L2 write-ingress cap.
// R8: overlap that 7us write with the 5.5us DRAM read via reader/writer CTA
// specialization. 512 reader CTAs stream 4 batches of 8 bh sequentially and
// signal per-bh counters; 128 writer CTAs start writing a bh as soon as its
// 64 partials are posted. No global barrier (R7's skew-serialization bug).

static constexpr int B_ = 4, H_ = 8, L_ = 2048, D_ = 64;
static constexpr int BH = B_ * H_;                 // 32
static constexpr int SPLITS = 64;                  // partials per bh
static constexpr int RROWS = L_ / SPLITS;          // 32 rows per reader-split
static constexpr int NBATCH = 4, BH_PER_BATCH = 8; // reader batching
static constexpr int NREAD = 512, NWRITE = 128;
static constexpr int NCTA = NREAD + NWRITE;        // 640 (all co-resident @5/SM)
static constexpr int SEGS = 4;                     // writer segs per bh
static constexpr int SEG_ROWS = L_ / SEGS;         // 512 rows per writer
static constexpr int STAGE_ROWS = 32;
static constexpr int STAGE_BYTES = STAGE_ROWS * D_ * 4; // 8192

__device__ float g_num[BH * SPLITS * D_];  // 512 KB partial numerators
__device__ float g_den[BH * SPLITS];
__device__ int   g_cnt[BH];       // readers arrive (0..64); reset by writers
__device__ int   g_consumed[BH];  // writer consumption count; reset by 4th

__device__ __forceinline__ float elu1(float x) {
    return x > 0.0f ? x + 1.0f : __expf(x);
}

struct SmemReader { float4 s_num[16][D_ / 4]; float s_den[16]; };
struct SmemWriter { float4 s_buf[STAGE_ROWS * (D_ / 4)]; float4 s_w4[D_ / 4]; };

__global__ __launch_bounds__(256, 5) void fused_kernel(
    const float* __restrict__ K, const float* __restrict__ V,
    float* __restrict__ out)
{
    __shared__ union { SmemReader r; SmemWriter w; } sm;
    const int t    = threadIdx.x;
    const int warp = t >> 5;
    const int lane = t & 31;
    const int half = lane >> 4;     // row of the pair
    const int q    = lane & 15;     // float4 slot within row

    if (blockIdx.x < NREAD) {
        // ------------------------- READER -------------------------------
        const int grp   = blockIdx.x / SPLITS;   // 0..7 (bh within batch)
        const int split = blockIdx.x % SPLITS;   // 0..63

        for (int b = 0; b < NBATCH; b++) {
            const int bh = b * BH_PER_BATCH + grp;
            // Warp covers 4 rows: split*32 + warp*4 + 2p + half, p in {0,1}.
            const size_t base = ((size_t)bh * L_ + split * RROWS
                                 + warp * 4 + half) * D_ + (size_t)q * 4;
            const float4* __restrict__ Kp = reinterpret_cast<const float4*>(K + base);
            const float4* __restrict__ Vp = reinterpret_cast<const float4*>(V + base);
            constexpr int STRIDE4 = 2 * D_ / 4;   // 2 rows in float4s

            float n0 = 0.f, n1 = 0.f, n2 = 0.f, n3 = 0.f, den = 0.f;
            #pragma unroll
            for (int p = 0; p < 2; p++) {
                float4 kk = Kp[p * STRIDE4];
                float4 vv = Vp[p * STRIDE4];
                float ks = elu1(kk.x) + elu1(kk.y) + elu1(kk.z) + elu1(kk.w);
                #pragma unroll
                for (int o = 8; o; o >>= 1)
                    ks += __shfl_xor_sync(0xffffffffu, ks, o);
                n0 += ks * vv.x;  n1 += ks * vv.y;
                n2 += ks * vv.z;  n3 += ks * vv.w;
                if (q == 0) den += ks;
            }

            const int wh = warp * 2 + half;       // 0..15
            sm.r.s_num[wh][q] = make_float4(n0, n1, n2, n3);
            if (q == 0) sm.r.s_den[wh] = den;
            __syncthreads();

            if (t < D_) {
                const float* sn = reinterpret_cast<const float*>(sm.r.s_num);
                float s = 0.0f;
                #pragma unroll
                for (int w = 0; w < 16; w++) s += sn[w * D_ + t];
                g_num[(bh * SPLITS + split) * D_ + t] = s;
            }
            if (t == D_) {
                float s = 0.0f;
                #pragma unroll
                for (int w = 0; w < 16; w++) s += sm.r.s_den[w];
                g_den[bh * SPLITS + split] = s;
            }
            __syncthreads();            // partials read before smem reuse
            if (t == 0) {               // canonical release: fence then arrive
                __threadfence();
                atomicAdd(&g_cnt[bh], 1);
            }
        }
    } else {
        // ------------------------- WRITER -------------------------------
        const int w   = blockIdx.x - NREAD;   // 0..127
        const int bh  = w >> 2;               // 0..31
        const int seg = w & 3;                // 0..3

        if (t == 0) {
            volatile int* p = &g_cnt[bh];
            while (*p < SPLITS) { __nanosleep(256); }
            __threadfence();                  // acquire
        }
        __syncthreads();

        if (t < D_) {
            float num = 0.0f, den = 0.0f;
            const float* __restrict__ pn = g_num + (bh * SPLITS) * D_ + t;
            #pragma unroll 8
            for (int s = 0; s < SPLITS; s++) {
                num += __ldcg(pn + s * D_);
                den += __ldcg(&g_den[bh * SPLITS + s]);
            }
            reinterpret_cast<float*>(sm.w.s_w4)[t] = num / den;
        }
        __syncthreads();

        // Replicate the 256B row into 32 staged rows (2 STS.128 each).
        {
            const float4 v = sm.w.s_w4[t & 15];
            const int r0 = t >> 4;            // 0..15
            sm.w.s_buf[r0 * (D_ / 4) + (t & 15)] = v;
            sm.w.s_buf[(r0 + 16) * (D_ / 4) + (t & 15)] = v;
        }
        __syncthreads();

        if (t == 0) {
            asm volatile("fence.proxy.async.shared::cta;" ::: "memory");
            uint32_t saddr = (uint32_t)__cvta_generic_to_shared(sm.w.s_buf);
            #pragma unroll
            for (int i = 0; i < SEG_ROWS / STAGE_ROWS; i++) {   // 16 copies
                const float* gdst = out + ((size_t)bh * L_
                    + (size_t)seg * SEG_ROWS + (size_t)i * STAGE_ROWS) * D_;
                asm volatile(
                    "cp.async.bulk.global.shared::cta.bulk_group [%0], [%1], %2;"
                    :: "l"(gdst), "r"(saddr), "r"((int)STAGE_BYTES) : "memory");
            }
            asm volatile("cp.async.bulk.commit_group;" ::: "memory");
            asm volatile("cp.async.bulk.wait_group.read 0;" ::: "memory");

            // 4th consumer of this bh resets counters for the next replay.
            int c = atomicAdd(&g_consumed[bh], 1);
            if (c == SEGS - 1) { g_cnt[bh] = 0; g_consumed[bh] = 0; }
        }
    }
}

extern "C" void kernel_launch(void* const* d_in, const int* in_sizes, int n_in,
                              void* d_out, int out_size)
{
    // metadata order: query, key, value. Query is mathematically irrelevant.
    const float* K = (const float*)d_in[1];
    const float* V = (const float*)d_in[2];
    float* out = (float*)d_out;

    fused_kernel<<<NCTA, 256>>>(K, V, out);
}

// round 9
// speedup vs baseline: 1.4625x; 1.4625x over previous
#include <cuda_runtime.h>
#include <cuda_bf16.h>
#include <cstdint>

// DotAttentionEluX — math collapses:
//   attn[i,j] = ks_j / sum_j ks_j  (query cancels in row normalization)
//   out[b,h,i,:] = (sum_j ks_j * v_j) / (sum_j ks_j)   -- same for every row i
// with ks_j = sum_d (elu(k[b,h,j,d]) + 1).
//
// R4-R6: write pins at ~7us/2.3TB/s for STG-only OR TMA-only. R7/R8: fusion
// regressions (barriered reads lose MLP). R9: proven 2-kernel structure;
// bcast splits the 16MB write across BOTH mechanisms concurrently (8MB via
// bulk-TMA CTAs, 8MB via STG.128 .cs CTAs) to test whether the two write
// paths have separate ingress caps.

static constexpr int B_ = 4, H_ = 8, L_ = 2048, D_ = 64;
static constexpr int BH = B_ * H_;                  // 32
static constexpr int NSPLIT = 16;
static constexpr int ROWS_PER_SPLIT = L_ / NSPLIT;  // 128
static constexpr int WARPS = 8;

__device__ float g_num[BH * NSPLIT * D_];
__device__ float g_den[BH * NSPLIT];

__device__ __forceinline__ float elu1(float x) {
    return x > 0.0f ? x + 1.0f : __expf(x);
}

// ---------------- accum: proven R6 version (float4 loads) ----------------
__global__ __launch_bounds__(256) void accum_kernel(
    const float* __restrict__ K, const float* __restrict__ V)
{
    const int blk   = blockIdx.x;       // 0..511
    const int bh    = blk / NSPLIT;
    const int split = blk % NSPLIT;
    const int warp  = threadIdx.x >> 5;
    const int lane  = threadIdx.x & 31;
    const int half  = lane >> 4;
    const int q     = lane & 15;

    const int row0 = split * ROWS_PER_SPLIT;
    const size_t base = ((size_t)bh * L_ + row0 + (size_t)warp * 2 + half) * D_
                        + (size_t)q * 4;
    const float4* __restrict__ Kp = reinterpret_cast<const float4*>(K + base);
    const float4* __restrict__ Vp = reinterpret_cast<const float4*>(V + base);
    constexpr int STRIDE4 = WARPS * 2 * D_ / 4;
    constexpr int NPAIR   = ROWS_PER_SPLIT / (WARPS * 2);   // 8

    float n0 = 0.f, n1 = 0.f, n2 = 0.f, n3 = 0.f, den = 0.f;

    #pragma unroll
    for (int r = 0; r < NPAIR; r++) {
        float4 kk = Kp[(size_t)r * STRIDE4];
        float4 vv = Vp[(size_t)r * STRIDE4];
        float ks = elu1(kk.x) + elu1(kk.y) + elu1(kk.z) + elu1(kk.w);
        #pragma unroll
        for (int o = 8; o; o >>= 1)
            ks += __shfl_xor_sync(0xffffffffu, ks, o);
        n0 += ks * vv.x;  n1 += ks * vv.y;
        n2 += ks * vv.z;  n3 += ks * vv.w;
        if (q == 0) den += ks;
    }

    __shared__ float4 s_num[WARPS * 2][D_ / 4];
    __shared__ float  s_den[WARPS * 2];
    const int wh = warp * 2 + half;
    s_num[wh][q] = make_float4(n0, n1, n2, n3);
    if (q == 0) s_den[wh] = den;
    __syncthreads();

    const int t = threadIdx.x;
    if (t < D_) {
        const float* sn = reinterpret_cast<const float*>(s_num);
        float s = 0.0f;
        #pragma unroll
        for (int w = 0; w < WARPS * 2; w++) s += sn[w * D_ + t];
        g_num[(bh * NSPLIT + split) * D_ + t] = s;
    }
    if (t == D_) {
        float s = 0.0f;
        #pragma unroll
        for (int w = 0; w < WARPS * 2; w++) s += s_den[w];
        g_den[bh * NSPLIT + split] = s;
    }
}

// ---------------- bcast: hybrid TMA + STG write paths ---------------------
static constexpr int NTMA = 256;   // TMA CTAs: bh 0..15, 16 CTAs/bh, 128 rows each
static constexpr int NSTG = 512;   // STG CTAs: bh 16..31, 32 CTAs/bh, 64 rows each
static constexpr int STAGE_ROWS = 32;
static constexpr int STAGE_BYTES = STAGE_ROWS * D_ * 4;   // 8192

__device__ __forceinline__ void reduce_w(int bh, int t, float* s_w) {
    if (t < D_) {
        const float* __restrict__ pn = g_num + bh * NSPLIT * D_ + t;
        float num = 0.0f, den = 0.0f;
        #pragma unroll
        for (int sp = 0; sp < NSPLIT; sp++) {
            num += __ldcg(pn + sp * D_);
            den += __ldcg(&g_den[bh * NSPLIT + sp]);
        }
        s_w[t] = num / den;
    }
}

__global__ __launch_bounds__(256) void bcast_kernel(float* __restrict__ out)
{
    const int t = threadIdx.x;
    __shared__ alignas(128) float4 s_buf[STAGE_ROWS * (D_ / 4)]; // 8 KB
    __shared__ float4 s_w4[D_ / 4];

    if (blockIdx.x < NTMA) {
        // ---- TMA half: bh 0..15 ----
        const int bh  = blockIdx.x >> 4;        // 0..15
        const int seg = blockIdx.x & 15;        // 0..15, 128 rows each
        reduce_w(bh, t, reinterpret_cast<float*>(s_w4));
        __syncthreads();

        {   // replicate into 32 staged rows (2 STS.128 per thread)
            const float4 v = s_w4[t & 15];
            const int r0 = t >> 4;              // 0..15
            s_buf[r0 * (D_ / 4) + (t & 15)] = v;
            s_buf[(r0 + 16) * (D_ / 4) + (t & 15)] = v;
        }
        __syncthreads();

        if (t == 0) {
            asm volatile("fence.proxy.async.shared::cta;" ::: "memory");
            uint32_t saddr = (uint32_t)__cvta_generic_to_shared(s_buf);
            #pragma unroll
            for (int i = 0; i < 4; i++) {       // 4 x 8KB = 128 rows
                const float* gdst = out + ((size_t)bh * L_
                    + (size_t)seg * 128 + (size_t)i * STAGE_ROWS) * D_;
                asm volatile(
                    "cp.async.bulk.global.shared::cta.bulk_group [%0], [%1], %2;"
                    :: "l"(gdst), "r"(saddr), "r"((int)STAGE_BYTES) : "memory");
            }
            asm volatile("cp.async.bulk.commit_group;" ::: "memory");
            asm volatile("cp.async.bulk.wait_group.read 0;" ::: "memory");
        }
    } else {
        // ---- STG half: bh 16..31 ----
        const int j   = blockIdx.x - NTMA;      // 0..511
        const int bh  = 16 + (j >> 5);          // 16..31
        const int seg = j & 31;                 // 0..31, 64 rows each
        reduce_w(bh, t, reinterpret_cast<float*>(s_w4));
        __syncthreads();

        const float4 v = s_w4[t & 15];
        float4* __restrict__ ob = reinterpret_cast<float4*>(
            out + ((size_t)bh * L_ + (size_t)seg * 64) * D_);
        // 64 rows * 16 float4 = 1024 stores; 256 threads x 4, coalesced.
        #pragma unroll
        for (int i = 0; i < 4; i++)
            __stcs(ob + t + i * 256, v);
    }
}

extern "C" void kernel_launch(void* const* d_in, const int* in_sizes, int n_in,
                              void* d_out, int out_size)
{
    // metadata order: query, key, value. Query is mathematically irrelevant.
    const float* K = (const float*)d_in[1];
    const float* V = (const float*)d_in[2];
    float* out = (float*)d_out;

    accum_kernel<<<BH * NSPLIT, 256>>>(K, V);
    bcast_kernel<<<NTMA + NSTG, 256>>>(out);
}